// round 4
// baseline (speedup 1.0000x reference)
#include <cuda_runtime.h>
#include <cuda_bf16.h>
#include <math.h>

// Problem constants
#define B_SZ   4
#define T_SEQ  2048
#define D_MOD  512
#define N_HEAD 8
#define HD     64
#define M_ROWS (B_SZ * T_SEQ)   // 8192

// ---------------- scratch (device globals; no runtime allocation) ----------
__device__ float g_QP[(size_t)M_ROWS * D_MOD];
__device__ float g_KP[(size_t)M_ROWS * D_MOD];
__device__ float g_VP[(size_t)M_ROWS * D_MOD];
__device__ float g_CTX[(size_t)M_ROWS * D_MOD];

// ---------------- GEMM + bias core: C[M,512] = A[M,512] @ W[512,512] + b ----
// BM=64, BN=64, BK=32, 256 threads, 4x4 per thread.
__device__ __forceinline__ void gemm_bias_body(
    const float* __restrict__ A, const float* __restrict__ W,
    const float* __restrict__ bias, float* __restrict__ C,
    int m0, int n0)
{
    constexpr int BK = 32, SA = 68;   // 68: float4-aligned, conflict-light
    __shared__ float As[BK * SA];
    __shared__ float Ws[BK * SA];

    const int tid = threadIdx.x;
    const int tx = tid & 15;       // N direction
    const int ty = tid >> 4;       // M direction

    float acc[4][4];
#pragma unroll
    for (int i = 0; i < 4; i++)
#pragma unroll
        for (int j = 0; j < 4; j++) acc[i][j] = 0.f;

    for (int kt = 0; kt < D_MOD; kt += BK) {
        __syncthreads();
        // load A tile [BM x BK] -> As[kk][m]  (coalesced in kk)
#pragma unroll
        for (int it = 0; it < 8; it++) {
            int idx = tid + it * 256;            // 0..2047
            int kk = idx & 31, m = idx >> 5;
            As[kk * SA + m] = A[(size_t)(m0 + m) * D_MOD + kt + kk];
        }
        // load W tile [BK x BN] -> Ws[kk][nn]  (fully coalesced)
#pragma unroll
        for (int it = 0; it < 8; it++) {
            int idx = tid + it * 256;
            int nn = idx & 63, kk = idx >> 6;
            Ws[kk * SA + nn] = W[(size_t)(kt + kk) * D_MOD + n0 + nn];
        }
        __syncthreads();
#pragma unroll
        for (int kk = 0; kk < BK; kk++) {
            float4 a4 = *(const float4*)(As + kk * SA + ty * 4);
            float4 w4 = *(const float4*)(Ws + kk * SA + tx * 4);
            float av[4] = {a4.x, a4.y, a4.z, a4.w};
            float wv[4] = {w4.x, w4.y, w4.z, w4.w};
#pragma unroll
            for (int i = 0; i < 4; i++)
#pragma unroll
                for (int j = 0; j < 4; j++)
                    acc[i][j] = fmaf(av[i], wv[j], acc[i][j]);
        }
    }

#pragma unroll
    for (int i = 0; i < 4; i++) {
        int m = m0 + ty * 4 + i;
#pragma unroll
        for (int j = 0; j < 4; j++) {
            int n = n0 + tx * 4 + j;
            C[(size_t)m * D_MOD + n] = acc[i][j] + bias[n];
        }
    }
}

// Fused projections: z=0 -> qp=q@Wq+bq ; z=1 -> kp=k@Wk+bk ; z=2 -> vp=v@Wk+bk
// (reference bug preserved: V projection uses Wk/bk)
__global__ __launch_bounds__(256) void proj_kernel(
    const float* __restrict__ q, const float* __restrict__ k,
    const float* __restrict__ v,
    const float* __restrict__ Wq, const float* __restrict__ bq,
    const float* __restrict__ Wk, const float* __restrict__ bk,
    float* __restrict__ QP, float* __restrict__ KP, float* __restrict__ VP)
{
    const int z = blockIdx.z;
    const float* A    = (z == 0) ? q  : (z == 1) ? k  : v;
    const float* W    = (z == 0) ? Wq : Wk;
    const float* bias = (z == 0) ? bq : bk;
    float*       C    = (z == 0) ? QP : (z == 1) ? KP : VP;
    gemm_bias_body(A, W, bias, C, blockIdx.x * 64, blockIdx.y * 64);
}

__global__ __launch_bounds__(256) void gemm_bias_kernel(
    const float* __restrict__ A, const float* __restrict__ W,
    const float* __restrict__ bias, float* __restrict__ C)
{
    gemm_bias_body(A, W, bias, C, blockIdx.x * 64, blockIdx.y * 64);
}

// ---------------- fused attention with head-axis softmax --------------------
// Grid: (T/TQ, B). 256 threads = 8 warps; warp h owns head h.
// Per CTA: TQ query rows; stream K/V in TK-row tiles.
// softmax over the 8 heads at each (q,k) position (exact, no streaming max).
#define TQ 16
#define TK 32
#define QS 520   // qp smem row stride (mult of 4 -> float4 ok; broadcast reads)
#define KS 513   // kp/vp smem row stride (odd -> conflict-free scalar access)
#define ATTN_SMEM_FLOATS (TQ*QS + 2*TK*KS + N_HEAD*TQ*TK)
#define ATTN_SMEM_BYTES  (ATTN_SMEM_FLOATS * 4)

__global__ __launch_bounds__(256, 1) void attn_kernel(
    const float* __restrict__ QP, const float* __restrict__ KP,
    const float* __restrict__ VP, float* __restrict__ CTX)
{
    extern __shared__ float sm[];
    float* qp_s = sm;                       // [TQ][QS]  (pre-scaled by 1/8)
    float* kp_s = qp_s + TQ * QS;           // [TK][KS]
    float* vp_s = kp_s + TK * KS;           // [TK][KS]
    float* at_s = vp_s + TK * KS;           // [H][TQ][TK]

    const int b   = blockIdx.y;
    const int q0  = blockIdx.x * TQ;
    const int tid = threadIdx.x;
    const int h   = tid >> 5;               // warp id = head
    const int lane = tid & 31;

    const float* QPb = QP + (size_t)(b * T_SEQ + q0) * D_MOD;
    const float* KPb = KP + (size_t)(b * T_SEQ) * D_MOD;
    const float* VPb = VP + (size_t)(b * T_SEQ) * D_MOD;

    // load Q tile once (float4, coalesced), fold in 1/sqrt(HD) = 0.125
    for (int i = tid; i < TQ * (D_MOD / 4); i += 256) {
        int r = i >> 7;                 // /128
        int c = (i & 127) << 2;
        float4 val = *(const float4*)(QPb + (size_t)r * D_MOD + c);
        val.x *= 0.125f; val.y *= 0.125f; val.z *= 0.125f; val.w *= 0.125f;
        *(float4*)(qp_s + r * QS + c) = val;
    }

    float O0[TQ], O1[TQ];
#pragma unroll
    for (int qi = 0; qi < TQ; qi++) { O0[qi] = 0.f; O1[qi] = 0.f; }

    for (int k0 = 0; k0 < T_SEQ; k0 += TK) {
        __syncthreads();    // previous O-phase done reading vp_s
        // load K,V tiles (float4 gmem, scalar smem stores due to KS=513)
        for (int i = tid; i < TK * (D_MOD / 4); i += 256) {
            int r = i >> 7;
            int c = (i & 127) << 2;
            float4 kv = *(const float4*)(KPb + (size_t)(k0 + r) * D_MOD + c);
            float* kd = kp_s + r * KS + c;
            kd[0] = kv.x; kd[1] = kv.y; kd[2] = kv.z; kd[3] = kv.w;
            float4 vv = *(const float4*)(VPb + (size_t)(k0 + r) * D_MOD + c);
            float* vd = vp_s + r * KS + c;
            vd[0] = vv.x; vd[1] = vv.y; vd[2] = vv.z; vd[3] = vv.w;
        }
        __syncthreads();

        // ---- S phase: warp h computes S[qi][ki=lane] for its head ----
        float S[TQ];
#pragma unroll
        for (int qi = 0; qi < TQ; qi++) S[qi] = 0.f;
        const float* kr = kp_s + lane * KS + h * HD;   // conflict-free (513 % 32 == 1)
        const float* qb = qp_s + h * HD;               // broadcast
#pragma unroll
        for (int d = 0; d < HD; d += 4) {
            float k0r = kr[d + 0], k1r = kr[d + 1];
            float k2r = kr[d + 2], k3r = kr[d + 3];
#pragma unroll
            for (int qi = 0; qi < TQ; qi++) {
                float4 qv = *(const float4*)(qb + qi * QS + d);
                S[qi] = fmaf(qv.x, k0r, fmaf(qv.y, k1r,
                        fmaf(qv.z, k2r, fmaf(qv.w, k3r, S[qi]))));
            }
        }
#pragma unroll
        for (int qi = 0; qi < TQ; qi++)
            at_s[(h * TQ + qi) * TK + lane] = S[qi];   // scale already in Q
        __syncthreads();

        // ---- softmax across the 8 heads at each (qi,ki) position ----
        for (int p = tid; p < TQ * TK; p += 256) {
            float v[N_HEAD];
            float mx = -1e30f;
#pragma unroll
            for (int hh = 0; hh < N_HEAD; hh++) {
                v[hh] = at_s[hh * TQ * TK + p];
                mx = fmaxf(mx, v[hh]);
            }
            float s = 0.f;
#pragma unroll
            for (int hh = 0; hh < N_HEAD; hh++) {
                v[hh] = __expf(v[hh] - mx);
                s += v[hh];
            }
            float r = 1.0f / s;
#pragma unroll
            for (int hh = 0; hh < N_HEAD; hh++)
                at_s[hh * TQ * TK + p] = v[hh] * r;
        }
        __syncthreads();

        // ---- O phase: O[qi][d] += sum_ki attn[h][qi][ki] * vp[ki][h*64+d] ----
        const float* vb = vp_s + h * HD + lane;   // conflict-free
#pragma unroll
        for (int kb = 0; kb < TK; kb += 4) {
            float v00 = vb[(kb + 0) * KS], v01 = vb[(kb + 0) * KS + 32];
            float v10 = vb[(kb + 1) * KS], v11 = vb[(kb + 1) * KS + 32];
            float v20 = vb[(kb + 2) * KS], v21 = vb[(kb + 2) * KS + 32];
            float v30 = vb[(kb + 3) * KS], v31 = vb[(kb + 3) * KS + 32];
#pragma unroll
            for (int qi = 0; qi < TQ; qi++) {
                float4 a = *(const float4*)(at_s + (h * TQ + qi) * TK + kb);
                O0[qi] = fmaf(a.x, v00, fmaf(a.y, v10,
                         fmaf(a.z, v20, fmaf(a.w, v30, O0[qi]))));
                O1[qi] = fmaf(a.x, v01, fmaf(a.y, v11,
                         fmaf(a.z, v21, fmaf(a.w, v31, O1[qi]))));
            }
        }
    }

    // write ctx (b, q, h*64 + d)
#pragma unroll
    for (int qi = 0; qi < TQ; qi++) {
        size_t row = (size_t)(b * T_SEQ + q0 + qi) * D_MOD;
        CTX[row + h * HD + lane]      = O0[qi];
        CTX[row + h * HD + lane + 32] = O1[qi];
    }
}

// ---------------- launch --------------------------------------------------
extern "C" void kernel_launch(void* const* d_in, const int* in_sizes, int n_in,
                              void* d_out, int out_size)
{
    const float* q  = (const float*)d_in[0];
    const float* k  = (const float*)d_in[1];
    const float* v  = (const float*)d_in[2];
    const float* Wq = (const float*)d_in[3];
    const float* bq = (const float*)d_in[4];
    const float* Wk = (const float*)d_in[5];
    const float* bk = (const float*)d_in[6];
    // d_in[7] = Wv, d_in[8] = bv : intentionally unused (reference bug preserved)
    const float* Wc = (const float*)d_in[9];
    const float* bc = (const float*)d_in[10];
    float* out = (float*)d_out;

    float *QPd, *KPd, *VPd, *CTXd;
    cudaGetSymbolAddress((void**)&QPd,  g_QP);
    cudaGetSymbolAddress((void**)&KPd,  g_KP);
    cudaGetSymbolAddress((void**)&VPd,  g_VP);
    cudaGetSymbolAddress((void**)&CTXd, g_CTX);

    cudaFuncSetAttribute(attn_kernel,
                         cudaFuncAttributeMaxDynamicSharedMemorySize,
                         ATTN_SMEM_BYTES);

    // fused projections: one launch, z picks {qp, kp, vp}
    dim3 pgrid(M_ROWS / 64, D_MOD / 64, 3);   // (128, 8, 3)
    proj_kernel<<<pgrid, 256>>>(q, k, v, Wq, bq, Wk, bk, QPd, KPd, VPd);

    // fused attention (head-axis softmax)
    attn_kernel<<<dim3(T_SEQ / TQ, B_SZ), 256, ATTN_SMEM_BYTES>>>(QPd, KPd, VPd, CTXd);

    // output projection
    dim3 ggrid(M_ROWS / 64, D_MOD / 64);      // (128, 8)
    gemm_bias_kernel<<<ggrid, 256>>>(CTXd, Wc, bc, out);
}

// round 7
// speedup vs baseline: 2.4208x; 2.4208x over previous
#include <cuda_runtime.h>
#include <cuda_bf16.h>
#include <math.h>
#include <stdint.h>

// Problem constants
#define B_SZ   4
#define T_SEQ  2048
#define D_MOD  512
#define N_HEAD 8
#define HD     64
#define M_ROWS (B_SZ * T_SEQ)   // 8192

// ---------------- scratch (device globals; no runtime allocation) ----------
__device__ float g_QP[(size_t)M_ROWS * D_MOD];
__device__ float g_KP[(size_t)M_ROWS * D_MOD];
__device__ float g_VP[(size_t)M_ROWS * D_MOD];
__device__ float g_CTX[(size_t)M_ROWS * D_MOD];

// ---------------- GEMM + bias core: C[M,512] = A[M,512] @ W[512,512] + b ----
__device__ __forceinline__ void gemm_bias_body(
    const float* __restrict__ A, const float* __restrict__ W,
    const float* __restrict__ bias, float* __restrict__ C,
    int m0, int n0)
{
    constexpr int BK = 32, SA = 68;
    __shared__ float As[BK * SA];
    __shared__ float Ws[BK * SA];

    const int tid = threadIdx.x;
    const int tx = tid & 15;
    const int ty = tid >> 4;

    float acc[4][4];
#pragma unroll
    for (int i = 0; i < 4; i++)
#pragma unroll
        for (int j = 0; j < 4; j++) acc[i][j] = 0.f;

    for (int kt = 0; kt < D_MOD; kt += BK) {
        __syncthreads();
#pragma unroll
        for (int it = 0; it < 8; it++) {
            int idx = tid + it * 256;
            int kk = idx & 31, m = idx >> 5;
            As[kk * SA + m] = A[(size_t)(m0 + m) * D_MOD + kt + kk];
        }
#pragma unroll
        for (int it = 0; it < 8; it++) {
            int idx = tid + it * 256;
            int nn = idx & 63, kk = idx >> 6;
            Ws[kk * SA + nn] = W[(size_t)(kt + kk) * D_MOD + n0 + nn];
        }
        __syncthreads();
#pragma unroll
        for (int kk = 0; kk < BK; kk++) {
            float4 a4 = *(const float4*)(As + kk * SA + ty * 4);
            float4 w4 = *(const float4*)(Ws + kk * SA + tx * 4);
            float av[4] = {a4.x, a4.y, a4.z, a4.w};
            float wv[4] = {w4.x, w4.y, w4.z, w4.w};
#pragma unroll
            for (int i = 0; i < 4; i++)
#pragma unroll
                for (int j = 0; j < 4; j++)
                    acc[i][j] = fmaf(av[i], wv[j], acc[i][j]);
        }
    }

#pragma unroll
    for (int i = 0; i < 4; i++) {
        int m = m0 + ty * 4 + i;
#pragma unroll
        for (int j = 0; j < 4; j++) {
            int n = n0 + tx * 4 + j;
            C[(size_t)m * D_MOD + n] = acc[i][j] + bias[n];
        }
    }
}

// z=0 -> qp=q@Wq+bq ; z=1 -> kp=k@Wk+bk ; z=2 -> vp=v@Wk+bk (ref bug kept)
__global__ __launch_bounds__(256) void proj_kernel(
    const float* __restrict__ q, const float* __restrict__ k,
    const float* __restrict__ v,
    const float* __restrict__ Wq, const float* __restrict__ bq,
    const float* __restrict__ Wk, const float* __restrict__ bk,
    float* __restrict__ QP, float* __restrict__ KP, float* __restrict__ VP)
{
    const int z = blockIdx.z;
    const float* A    = (z == 0) ? q  : (z == 1) ? k  : v;
    const float* W    = (z == 0) ? Wq : Wk;
    const float* bias = (z == 0) ? bq : bk;
    float*       C    = (z == 0) ? QP : (z == 1) ? KP : VP;
    gemm_bias_body(A, W, bias, C, blockIdx.x * 64, blockIdx.y * 64);
}

__global__ __launch_bounds__(256) void gemm_bias_kernel(
    const float* __restrict__ A, const float* __restrict__ W,
    const float* __restrict__ bias, float* __restrict__ C)
{
    gemm_bias_body(A, W, bias, C, blockIdx.x * 64, blockIdx.y * 64);
}

// =====================  tf32 MMA attention  =================================
// Grid (T/TQa, B), 256 threads = 8 warps, warp h = head h.
// Per k-tile (TKa keys): S = Qh@Kh^T (tf32 mma), head-axis softmax, O += P@Vh.
// K/V double-buffered in smem via cp.async; Q lives in registers as fragments.
#define TQa 32
#define TKa 16
#define KVS 68                         // per-head row stride (conflict-free frags)
#define ATS 20                         // at_s row stride (conflict-free frags)
#define KVBUF (N_HEAD * TKa * KVS)     // 8704 floats per (buf, K-or-V)
#define AT_FLOATS (N_HEAD * TQa * ATS) // 5120
#define ATTN_SMEM_FLOATS (4 * KVBUF + AT_FLOATS)   // 39936
#define ATTN_SMEM_BYTES  (ATTN_SMEM_FLOATS * 4)    // 159744
#define NKT (T_SEQ / TKa)              // 128 k-tiles

__device__ __forceinline__ uint32_t f2tf32(float f) {
    uint32_t u;
    asm("cvt.rna.tf32.f32 %0, %1;" : "=r"(u) : "f"(f));
    return u;
}
__device__ __forceinline__ void mma_tf32(float d[4], const uint32_t a[4],
                                         uint32_t b0, uint32_t b1) {
    asm volatile(
        "mma.sync.aligned.m16n8k8.row.col.f32.tf32.tf32.f32 "
        "{%0,%1,%2,%3}, {%4,%5,%6,%7}, {%8,%9}, {%0,%1,%2,%3};\n"
        : "+f"(d[0]), "+f"(d[1]), "+f"(d[2]), "+f"(d[3])
        : "r"(a[0]), "r"(a[1]), "r"(a[2]), "r"(a[3]), "r"(b0), "r"(b1));
}
__device__ __forceinline__ void cp16(uint32_t dst, const float* src) {
    asm volatile("cp.async.cg.shared.global [%0], [%1], 16;"
                 :: "r"(dst), "l"(src));
}
#define CP_COMMIT() asm volatile("cp.async.commit_group;")
#define CP_WAIT0()  asm volatile("cp.async.wait_group 0;" ::: "memory")

// stage tile t's K/V rows into buffer bufsel ([H][TKa][KVS] per-head layout)
__device__ __forceinline__ void issue_kv_tile(
    uint32_t smem0, int bufsel,
    const float* __restrict__ Kt, const float* __restrict__ Vt, int tid)
{
#pragma unroll
    for (int j = 0; j < 8; ++j) {
        int idx = tid + j * 256;          // float4 index, 0..2047
        int kr  = idx >> 7;               // key row 0..15
        int c4  = idx & 127;              // float4 col within 512
        int hh  = c4 >> 4;                // head
        int d   = (c4 & 15) << 2;         // dim within head
        uint32_t off = (uint32_t)((bufsel * 2 * KVBUF +
                                   (hh * TKa + kr) * KVS + d) << 2);
        const float* gsrc = Kt + (size_t)kr * D_MOD + (c4 << 2);
        cp16(smem0 + off, gsrc);
        const float* gsrcv = Vt + (size_t)kr * D_MOD + (c4 << 2);
        cp16(smem0 + off + (KVBUF << 2), gsrcv);
    }
}

__global__ __launch_bounds__(256, 1) void attn_mma_kernel(
    const float* __restrict__ QP, const float* __restrict__ KP,
    const float* __restrict__ VP, float* __restrict__ CTX)
{
    extern __shared__ float sm[];
    float* kv   = sm;                     // [2 bufs][K,V][KVBUF]
    float* at_s = sm + 4 * KVBUF;         // [H][TQa][ATS]

    const int b    = blockIdx.y;
    const int q0   = blockIdx.x * TQa;
    const int tid  = threadIdx.x;
    const int h    = tid >> 5;
    const int lane = tid & 31;
    const int g    = lane >> 2;           // fragment group row / n
    const int k4   = lane & 3;            // fragment k index

    uint32_t smem0;
    asm("{.reg .u64 t; cvta.to.shared.u64 t, %1; cvt.u32.u64 %0, t;}"
        : "=r"(smem0) : "l"(sm));

    const float* KPb = KP + (size_t)(b * T_SEQ) * D_MOD;
    const float* VPb = VP + (size_t)(b * T_SEQ) * D_MOD;

    // ---- Q fragments in registers (scaled by 1/sqrt(64), tf32-rounded) ----
    uint32_t qf[2][8][4];
    {
        const float* Qb = QP + ((size_t)(b * T_SEQ) + q0) * D_MOD + h * HD;
#pragma unroll
        for (int mt = 0; mt < 2; mt++) {
            int r0 = mt * 16 + g;
#pragma unroll
            for (int ks = 0; ks < 8; ks++) {
                int c0 = ks * 8 + k4;
                qf[mt][ks][0] = f2tf32(Qb[(size_t)r0 * D_MOD + c0] * 0.125f);
                qf[mt][ks][1] = f2tf32(Qb[(size_t)(r0 + 8) * D_MOD + c0] * 0.125f);
                qf[mt][ks][2] = f2tf32(Qb[(size_t)r0 * D_MOD + c0 + 4] * 0.125f);
                qf[mt][ks][3] = f2tf32(Qb[(size_t)(r0 + 8) * D_MOD + c0 + 4] * 0.125f);
            }
        }
    }

    float o[2][8][4];
#pragma unroll
    for (int mt = 0; mt < 2; mt++)
#pragma unroll
        for (int nt = 0; nt < 8; nt++)
#pragma unroll
            for (int r = 0; r < 4; r++) o[mt][nt][r] = 0.f;

    float* ah = at_s + h * TQa * ATS;

    // prologue: stage tile 0
    issue_kv_tile(smem0, 0, KPb, VPb, tid);
    CP_COMMIT();

    for (int t = 0; t < NKT; ++t) {
        const int cur = t & 1;
        CP_WAIT0();
        __syncthreads();     // tile t visible everywhere; compute(t-1) done
        if (t + 1 < NKT) {   // prefetch next tile, overlaps compute below
            issue_kv_tile(smem0, cur ^ 1,
                          KPb + (size_t)(t + 1) * TKa * D_MOD,
                          VPb + (size_t)(t + 1) * TKa * D_MOD, tid);
            CP_COMMIT();
        }

        // ---- S = Qh @ Kh^T  (M=32, N=16, K=64) ----
        const float* kp = kv + cur * 2 * KVBUF + h * TKa * KVS;
        float s[2][2][4];
#pragma unroll
        for (int mt = 0; mt < 2; mt++)
#pragma unroll
            for (int nt = 0; nt < 2; nt++)
#pragma unroll
                for (int r = 0; r < 4; r++) s[mt][nt][r] = 0.f;
#pragma unroll
        for (int ks = 0; ks < 8; ks++) {
#pragma unroll
            for (int nt = 0; nt < 2; nt++) {
                int nrow = nt * 8 + g;
                uint32_t b0 = __float_as_uint(kp[nrow * KVS + ks * 8 + k4]);
                uint32_t b1 = __float_as_uint(kp[nrow * KVS + ks * 8 + k4 + 4]);
                mma_tf32(s[0][nt], qf[0][ks], b0, b1);
                mma_tf32(s[1][nt], qf[1][ks], b0, b1);
            }
        }
        // write S to at_s  (c-frag: rows g/g+8, cols 2*k4/2*k4+1)
#pragma unroll
        for (int mt = 0; mt < 2; mt++) {
            int r0 = mt * 16 + g;
#pragma unroll
            for (int nt = 0; nt < 2; nt++) {
                int ki = nt * 8 + 2 * k4;
                *(float2*)(ah + r0 * ATS + ki)       = make_float2(s[mt][nt][0], s[mt][nt][1]);
                *(float2*)(ah + (r0 + 8) * ATS + ki) = make_float2(s[mt][nt][2], s[mt][nt][3]);
            }
        }
        __syncthreads();

        // ---- softmax across the 8 heads at each (qi,ki) ----
        for (int p = tid; p < TQa * TKa; p += 256) {
            int off = (p >> 4) * ATS + (p & 15);
            float v[N_HEAD];
            float mx = -1e30f;
#pragma unroll
            for (int hh = 0; hh < N_HEAD; hh++) {
                v[hh] = at_s[hh * (TQa * ATS) + off];
                mx = fmaxf(mx, v[hh]);
            }
            float ssum = 0.f;
#pragma unroll
            for (int hh = 0; hh < N_HEAD; hh++) {
                v[hh] = __expf(v[hh] - mx);
                ssum += v[hh];
            }
            float rr = 1.0f / ssum;
#pragma unroll
            for (int hh = 0; hh < N_HEAD; hh++)
                at_s[hh * (TQa * ATS) + off] =
                    __uint_as_float(f2tf32(v[hh] * rr));
        }
        __syncthreads();

        // ---- O += P @ Vh  (M=32, N=64, K=16) ----
        const float* vp = kv + cur * 2 * KVBUF + KVBUF + h * TKa * KVS;
#pragma unroll
        for (int ks2 = 0; ks2 < 2; ks2++) {
            uint32_t af[2][4];
#pragma unroll
            for (int mt = 0; mt < 2; mt++) {
                int r0 = mt * 16 + g;
                int ki = ks2 * 8 + k4;
                af[mt][0] = __float_as_uint(ah[r0 * ATS + ki]);
                af[mt][1] = __float_as_uint(ah[(r0 + 8) * ATS + ki]);
                af[mt][2] = __float_as_uint(ah[r0 * ATS + ki + 4]);
                af[mt][3] = __float_as_uint(ah[(r0 + 8) * ATS + ki + 4]);
            }
#pragma unroll
            for (int nt = 0; nt < 8; nt++) {
                uint32_t b0 = __float_as_uint(vp[(ks2 * 8 + k4) * KVS + nt * 8 + g]);
                uint32_t b1 = __float_as_uint(vp[(ks2 * 8 + k4 + 4) * KVS + nt * 8 + g]);
                mma_tf32(o[0][nt], af[0], b0, b1);
                mma_tf32(o[1][nt], af[1], b0, b1);
            }
        }
        __syncthreads();   // O done reading buffers/at_s before next overwrite
    }

    // ---- epilogue: write ctx ----
#pragma unroll
    for (int mt = 0; mt < 2; mt++) {
        size_t row0 = (size_t)(b * T_SEQ + q0 + mt * 16 + g) * D_MOD;
        size_t row1 = row0 + 8 * D_MOD;
#pragma unroll
        for (int nt = 0; nt < 8; nt++) {
            int col = h * HD + nt * 8 + 2 * k4;
            *(float2*)(CTX + row0 + col) = make_float2(o[mt][nt][0], o[mt][nt][1]);
            *(float2*)(CTX + row1 + col) = make_float2(o[mt][nt][2], o[mt][nt][3]);
        }
    }
}

// ---------------- launch --------------------------------------------------
extern "C" void kernel_launch(void* const* d_in, const int* in_sizes, int n_in,
                              void* d_out, int out_size)
{
    const float* q  = (const float*)d_in[0];
    const float* k  = (const float*)d_in[1];
    const float* v  = (const float*)d_in[2];
    const float* Wq = (const float*)d_in[3];
    const float* bq = (const float*)d_in[4];
    const float* Wk = (const float*)d_in[5];
    const float* bk = (const float*)d_in[6];
    // d_in[7]=Wv, d_in[8]=bv : intentionally unused (reference bug preserved)
    const float* Wc = (const float*)d_in[9];
    const float* bc = (const float*)d_in[10];
    float* out = (float*)d_out;

    float *QPd, *KPd, *VPd, *CTXd;
    cudaGetSymbolAddress((void**)&QPd,  g_QP);
    cudaGetSymbolAddress((void**)&KPd,  g_KP);
    cudaGetSymbolAddress((void**)&VPd,  g_VP);
    cudaGetSymbolAddress((void**)&CTXd, g_CTX);

    cudaFuncSetAttribute(attn_mma_kernel,
                         cudaFuncAttributeMaxDynamicSharedMemorySize,
                         ATTN_SMEM_BYTES);

    dim3 pgrid(M_ROWS / 64, D_MOD / 64, 3);   // (128, 8, 3)
    proj_kernel<<<pgrid, 256>>>(q, k, v, Wq, bq, Wk, bk, QPd, KPd, VPd);

    attn_mma_kernel<<<dim3(T_SEQ / TQa, B_SZ), 256, ATTN_SMEM_BYTES>>>(
        QPd, KPd, VPd, CTXd);

    dim3 ggrid(M_ROWS / 64, D_MOD / 64);      // (128, 8)
    gemm_bias_kernel<<<ggrid, 256>>>(CTXd, Wc, bc, out);
}

// round 15
// speedup vs baseline: 3.3199x; 1.3714x over previous
#include <cuda_runtime.h>
#include <cuda_bf16.h>
#include <math.h>
#include <stdint.h>

// Problem constants
#define B_SZ   4
#define T_SEQ  2048
#define D_MOD  512
#define N_HEAD 8
#define HD     64
#define M_ROWS (B_SZ * T_SEQ)   // 8192
#define W_ELEMS (D_MOD * D_MOD) // 262144

// ---------------- scratch (device globals; no runtime allocation) ----------
__device__ float g_QP[(size_t)M_ROWS * D_MOD];
__device__ float g_KP[(size_t)M_ROWS * D_MOD];
__device__ float g_VP[(size_t)M_ROWS * D_MOD];
__device__ float g_CTX[(size_t)M_ROWS * D_MOD];
__device__ float g_Whi[3 * W_ELEMS];   // split weights: 0=Wq, 1=Wk, 2=Wc
__device__ float g_Wlo[3 * W_ELEMS];

// ---------------- common PTX helpers ---------------------------------------
__device__ __forceinline__ uint32_t f2tf32(float f) {
    uint32_t u;
    asm("cvt.rna.tf32.f32 %0, %1;" : "=r"(u) : "f"(f));
    return u;
}
__device__ __forceinline__ void mma_tf32(float d[4], const uint32_t a[4],
                                         uint32_t b0, uint32_t b1) {
    asm volatile(
        "mma.sync.aligned.m16n8k8.row.col.f32.tf32.tf32.f32 "
        "{%0,%1,%2,%3}, {%4,%5,%6,%7}, {%8,%9}, {%0,%1,%2,%3};\n"
        : "+f"(d[0]), "+f"(d[1]), "+f"(d[2]), "+f"(d[3])
        : "r"(a[0]), "r"(a[1]), "r"(a[2]), "r"(a[3]), "r"(b0), "r"(b1));
}
__device__ __forceinline__ void cp16(uint32_t dst, const float* src) {
    asm volatile("cp.async.cg.shared.global [%0], [%1], 16;"
                 :: "r"(dst), "l"(src));
}
#define CP_COMMIT() asm volatile("cp.async.commit_group;")
#define CP_WAIT0()  asm volatile("cp.async.wait_group 0;" ::: "memory")
__device__ __forceinline__ uint32_t sptr(const void* p) {
    uint32_t r;
    asm("{.reg .u64 t; cvta.to.shared.u64 t, %1; cvt.u32.u64 %0, t;}"
        : "=r"(r) : "l"(p));
    return r;
}

// ---------------- weight split prep: Whi = rna(W), Wlo = rna(W - Whi) ------
__global__ __launch_bounds__(256) void split_w_kernel(
    const float* __restrict__ Wq, const float* __restrict__ Wk,
    const float* __restrict__ Wc,
    float* __restrict__ Whi, float* __restrict__ Wlo)
{
    int i = blockIdx.x * 256 + threadIdx.x;     // 0 .. 3*W_ELEMS-1
    int z = i / W_ELEMS;
    int j = i - z * W_ELEMS;
    const float* src = (z == 0) ? Wq : (z == 1) ? Wk : Wc;
    float w  = src[j];
    float hi = __uint_as_float(f2tf32(w));
    float lo = __uint_as_float(f2tf32(w - hi));
    Whi[i] = hi;
    Wlo[i] = lo;
}

// ==== 2xTF32 split GEMM + bias: C[M,512] = A@W + b  (W = Whi + Wlo) ========
// BM=128, BN=128, BK=16; 256 thr = 8 warps (2x4), warp tile 64x32.
// A: rna-converted at fragment load. W: accumulated as A*Whi + A*Wlo.
// A smem stride 20 (banks 20g+k4 distinct); W smem stride 136 (8k4+g distinct).
#define GBM 128
#define GBN 128
#define GBK 16
#define GAS 20
#define GWS 136
// dynamic smem layout (floats): As[2][GBM*GAS] | Wh[2][GBK*GWS] | Wl[2][GBK*GWS]
#define GSM_WH (2 * GBM * GAS)                 // 5120
#define GSM_WL (GSM_WH + 2 * GBK * GWS)        // 9472
#define GSM_FLOATS (GSM_WL + 2 * GBK * GWS)    // 13824
#define GSM_BYTES (GSM_FLOATS * 4)             // 55296

__device__ __forceinline__ void gemm_issue(
    uint32_t s0, int buf,
    const float* __restrict__ A, const float* __restrict__ Wh,
    const float* __restrict__ Wl,
    int m0, int n0, int kt, int tid)
{
#pragma unroll
    for (int j = 0; j < 2; j++) {
        int idx = tid + j * 256;              // 0..511
        int m  = idx >> 2,  c4 = (idx & 3) << 2;
        cp16(s0 + (uint32_t)((buf * GBM * GAS + m * GAS + c4) << 2),
             A + (size_t)(m0 + m) * D_MOD + kt * GBK + c4);
        int kk = idx >> 5,  n4 = (idx & 31) << 2;
        size_t woff = (size_t)(kt * GBK + kk) * D_MOD + n0 + n4;
        cp16(s0 + (uint32_t)((GSM_WH + buf * GBK * GWS + kk * GWS + n4) << 2),
             Wh + woff);
        cp16(s0 + (uint32_t)((GSM_WL + buf * GBK * GWS + kk * GWS + n4) << 2),
             Wl + woff);
    }
}

__device__ __forceinline__ void gemm_split_body(
    const float* __restrict__ A, const float* __restrict__ Wh,
    const float* __restrict__ Wl, const float* __restrict__ bias,
    float* __restrict__ C, int m0, int n0)
{
    extern __shared__ float gsm[];

    const int tid  = threadIdx.x;
    const int wid  = tid >> 5;
    const int lane = tid & 31;
    const int wm   = (wid >> 2) * 64;     // 0 / 64
    const int wn   = (wid & 3) * 32;      // 0..96
    const int g    = lane >> 2;
    const int k4   = lane & 3;

    const uint32_t s0 = sptr(gsm);

    float c[4][4][4];
#pragma unroll
    for (int mt = 0; mt < 4; mt++)
#pragma unroll
        for (int nt = 0; nt < 4; nt++)
#pragma unroll
            for (int r = 0; r < 4; r++) c[mt][nt][r] = 0.f;

    gemm_issue(s0, 0, A, Wh, Wl, m0, n0, 0, tid);
    CP_COMMIT();

    for (int kt = 0; kt < D_MOD / GBK; kt++) {
        const int buf = kt & 1;
        CP_WAIT0();
        __syncthreads();
        if (kt + 1 < D_MOD / GBK) {
            gemm_issue(s0, buf ^ 1, A, Wh, Wl, m0, n0, kt + 1, tid);
            CP_COMMIT();
        }
        const float* a  = gsm + buf * GBM * GAS;
        const float* wh = gsm + GSM_WH + buf * GBK * GWS;
        const float* wl = gsm + GSM_WL + buf * GBK * GWS;
#pragma unroll
        for (int kk = 0; kk < 2; kk++) {
            uint32_t af[4][4], bh[4][2], bl[4][2];
#pragma unroll
            for (int mt = 0; mt < 4; mt++) {
                const float* ar = a + (wm + mt * 16 + g) * GAS + kk * 8 + k4;
                af[mt][0] = f2tf32(ar[0]);
                af[mt][1] = f2tf32(ar[8 * GAS]);
                af[mt][2] = f2tf32(ar[4]);
                af[mt][3] = f2tf32(ar[8 * GAS + 4]);
            }
#pragma unroll
            for (int nt = 0; nt < 4; nt++) {
                int off = (kk * 8 + k4) * GWS + wn + nt * 8 + g;
                bh[nt][0] = __float_as_uint(wh[off]);
                bh[nt][1] = __float_as_uint(wh[off + 4 * GWS]);
                bl[nt][0] = __float_as_uint(wl[off]);
                bl[nt][1] = __float_as_uint(wl[off + 4 * GWS]);
            }
#pragma unroll
            for (int mt = 0; mt < 4; mt++)
#pragma unroll
                for (int nt = 0; nt < 4; nt++) {
                    mma_tf32(c[mt][nt], af[mt], bh[nt][0], bh[nt][1]);
                    mma_tf32(c[mt][nt], af[mt], bl[nt][0], bl[nt][1]);
                }
        }
        // no trailing barrier: next top-of-loop sync orders reads before reuse
    }

    // epilogue: add bias, write (c-frag rows g/g+8, cols 2k4/2k4+1)
#pragma unroll
    for (int mt = 0; mt < 4; mt++) {
        int r0 = m0 + wm + mt * 16 + g;
#pragma unroll
        for (int nt = 0; nt < 4; nt++) {
            int nc = n0 + wn + nt * 8 + 2 * k4;
            float b0v = bias[nc], b1v = bias[nc + 1];
            *(float2*)(C + (size_t)r0 * D_MOD + nc) =
                make_float2(c[mt][nt][0] + b0v, c[mt][nt][1] + b1v);
            *(float2*)(C + (size_t)(r0 + 8) * D_MOD + nc) =
                make_float2(c[mt][nt][2] + b0v, c[mt][nt][3] + b1v);
        }
    }
}

// z=0 -> qp=q@Wq+bq ; z=1 -> kp=k@Wk+bk ; z=2 -> vp=v@Wk+bk (ref bug kept)
__global__ __launch_bounds__(256, 2) void proj_kernel(
    const float* __restrict__ q, const float* __restrict__ k,
    const float* __restrict__ v,
    const float* __restrict__ Whi, const float* __restrict__ Wlo,
    const float* __restrict__ bq, const float* __restrict__ bk,
    float* __restrict__ QP, float* __restrict__ KP, float* __restrict__ VP)
{
    const int z = blockIdx.z;
    const float* A    = (z == 0) ? q  : (z == 1) ? k  : v;
    const float* Wh   = Whi + (size_t)((z == 0) ? 0 : 1) * W_ELEMS;
    const float* Wl   = Wlo + (size_t)((z == 0) ? 0 : 1) * W_ELEMS;
    const float* bias = (z == 0) ? bq : bk;
    float*       C    = (z == 0) ? QP : (z == 1) ? KP : VP;
    gemm_split_body(A, Wh, Wl, bias, C, blockIdx.x * GBM, blockIdx.y * GBN);
}

__global__ __launch_bounds__(256, 2) void out_gemm_kernel(
    const float* __restrict__ A,
    const float* __restrict__ Whi, const float* __restrict__ Wlo,
    const float* __restrict__ bias, float* __restrict__ C)
{
    gemm_split_body(A, Whi + 2 * (size_t)W_ELEMS, Wlo + 2 * (size_t)W_ELEMS,
                    bias, C, blockIdx.x * GBM, blockIdx.y * GBN);
}

// =====================  tf32 MMA attention (unchanged, validated) ===========
#define TQa 32
#define TKa 16
#define KVS 68                         // per-head row stride (conflict-free frags)
#define ATS 20                         // at_s row stride (conflict-free frags)
#define KVBUF (N_HEAD * TKa * KVS)     // 8704 floats per (buf, K-or-V)
#define AT_FLOATS (N_HEAD * TQa * ATS) // 5120
#define ATTN_SMEM_FLOATS (4 * KVBUF + AT_FLOATS)   // 39936
#define ATTN_SMEM_BYTES  (ATTN_SMEM_FLOATS * 4)    // 159744
#define NKT (T_SEQ / TKa)              // 128 k-tiles

__device__ __forceinline__ void issue_kv_tile(
    uint32_t smem0, int bufsel,
    const float* __restrict__ Kt, const float* __restrict__ Vt, int tid)
{
#pragma unroll
    for (int j = 0; j < 8; ++j) {
        int idx = tid + j * 256;          // float4 index, 0..2047
        int kr  = idx >> 7;               // key row 0..15
        int c4  = idx & 127;              // float4 col within 512
        int hh  = c4 >> 4;                // head
        int d   = (c4 & 15) << 2;         // dim within head
        uint32_t off = (uint32_t)((bufsel * 2 * KVBUF +
                                   (hh * TKa + kr) * KVS + d) << 2);
        const float* gsrc = Kt + (size_t)kr * D_MOD + (c4 << 2);
        cp16(smem0 + off, gsrc);
        const float* gsrcv = Vt + (size_t)kr * D_MOD + (c4 << 2);
        cp16(smem0 + off + (KVBUF << 2), gsrcv);
    }
}

__global__ __launch_bounds__(256, 1) void attn_mma_kernel(
    const float* __restrict__ QP, const float* __restrict__ KP,
    const float* __restrict__ VP, float* __restrict__ CTX)
{
    extern __shared__ float sm[];
    float* kv   = sm;                     // [2 bufs][K,V][KVBUF]
    float* at_s = sm + 4 * KVBUF;         // [H][TQa][ATS]

    const int b    = blockIdx.y;
    const int q0   = blockIdx.x * TQa;
    const int tid  = threadIdx.x;
    const int h    = tid >> 5;
    const int lane = tid & 31;
    const int g    = lane >> 2;           // fragment group row / n
    const int k4   = lane & 3;            // fragment k index

    const uint32_t smem0 = sptr(sm);

    const float* KPb = KP + (size_t)(b * T_SEQ) * D_MOD;
    const float* VPb = VP + (size_t)(b * T_SEQ) * D_MOD;

    // ---- Q fragments in registers (scaled by 1/sqrt(64), tf32-rounded) ----
    uint32_t qf[2][8][4];
    {
        const float* Qb = QP + ((size_t)(b * T_SEQ) + q0) * D_MOD + h * HD;
#pragma unroll
        for (int mt = 0; mt < 2; mt++) {
            int r0 = mt * 16 + g;
#pragma unroll
            for (int ks = 0; ks < 8; ks++) {
                int c0 = ks * 8 + k4;
                qf[mt][ks][0] = f2tf32(Qb[(size_t)r0 * D_MOD + c0] * 0.125f);
                qf[mt][ks][1] = f2tf32(Qb[(size_t)(r0 + 8) * D_MOD + c0] * 0.125f);
                qf[mt][ks][2] = f2tf32(Qb[(size_t)r0 * D_MOD + c0 + 4] * 0.125f);
                qf[mt][ks][3] = f2tf32(Qb[(size_t)(r0 + 8) * D_MOD + c0 + 4] * 0.125f);
            }
        }
    }

    float o[2][8][4];
#pragma unroll
    for (int mt = 0; mt < 2; mt++)
#pragma unroll
        for (int nt = 0; nt < 8; nt++)
#pragma unroll
            for (int r = 0; r < 4; r++) o[mt][nt][r] = 0.f;

    float* ah = at_s + h * TQa * ATS;

    // prologue: stage tile 0
    issue_kv_tile(smem0, 0, KPb, VPb, tid);
    CP_COMMIT();

    for (int t = 0; t < NKT; ++t) {
        const int cur = t & 1;
        CP_WAIT0();
        __syncthreads();     // tile t visible; O(t-1) complete everywhere
        if (t + 1 < NKT) {   // prefetch next tile, overlaps compute below
            issue_kv_tile(smem0, cur ^ 1,
                          KPb + (size_t)(t + 1) * TKa * D_MOD,
                          VPb + (size_t)(t + 1) * TKa * D_MOD, tid);
            CP_COMMIT();
        }

        // ---- S = Qh @ Kh^T  (M=32, N=16, K=64) ----
        const float* kp = kv + cur * 2 * KVBUF + h * TKa * KVS;
        float s[2][2][4];
#pragma unroll
        for (int mt = 0; mt < 2; mt++)
#pragma unroll
            for (int nt = 0; nt < 2; nt++)
#pragma unroll
                for (int r = 0; r < 4; r++) s[mt][nt][r] = 0.f;
#pragma unroll
        for (int ks = 0; ks < 8; ks++) {
#pragma unroll
            for (int nt = 0; nt < 2; nt++) {
                int nrow = nt * 8 + g;
                uint32_t b0 = __float_as_uint(kp[nrow * KVS + ks * 8 + k4]);
                uint32_t b1 = __float_as_uint(kp[nrow * KVS + ks * 8 + k4 + 4]);
                mma_tf32(s[0][nt], qf[0][ks], b0, b1);
                mma_tf32(s[1][nt], qf[1][ks], b0, b1);
            }
        }
        // write S to at_s  (c-frag: rows g/g+8, cols 2*k4/2*k4+1)
#pragma unroll
        for (int mt = 0; mt < 2; mt++) {
            int r0 = mt * 16 + g;
#pragma unroll
            for (int nt = 0; nt < 2; nt++) {
                int ki = nt * 8 + 2 * k4;
                *(float2*)(ah + r0 * ATS + ki)       = make_float2(s[mt][nt][0], s[mt][nt][1]);
                *(float2*)(ah + (r0 + 8) * ATS + ki) = make_float2(s[mt][nt][2], s[mt][nt][3]);
            }
        }
        __syncthreads();

        // ---- softmax across the 8 heads at each (qi,ki) ----
        for (int p = tid; p < TQa * TKa; p += 256) {
            int off = (p >> 4) * ATS + (p & 15);
            float v[N_HEAD];
            float mx = -1e30f;
#pragma unroll
            for (int hh = 0; hh < N_HEAD; hh++) {
                v[hh] = at_s[hh * (TQa * ATS) + off];
                mx = fmaxf(mx, v[hh]);
            }
            float ssum = 0.f;
#pragma unroll
            for (int hh = 0; hh < N_HEAD; hh++) {
                v[hh] = __expf(v[hh] - mx);
                ssum += v[hh];
            }
            float rr = 1.0f / ssum;
#pragma unroll
            for (int hh = 0; hh < N_HEAD; hh++)
                at_s[hh * (TQa * ATS) + off] =
                    __uint_as_float(f2tf32(v[hh] * rr));
        }
        __syncthreads();

        // ---- O += P @ Vh  (M=32, N=64, K=16) ----
        const float* vp = kv + cur * 2 * KVBUF + KVBUF + h * TKa * KVS;
#pragma unroll
        for (int ks2 = 0; ks2 < 2; ks2++) {
            uint32_t af[2][4];
#pragma unroll
            for (int mt = 0; mt < 2; mt++) {
                int r0 = mt * 16 + g;
                int ki = ks2 * 8 + k4;
                af[mt][0] = __float_as_uint(ah[r0 * ATS + ki]);
                af[mt][1] = __float_as_uint(ah[(r0 + 8) * ATS + ki]);
                af[mt][2] = __float_as_uint(ah[r0 * ATS + ki + 4]);
                af[mt][3] = __float_as_uint(ah[(r0 + 8) * ATS + ki + 4]);
            }
#pragma unroll
            for (int nt = 0; nt < 8; nt++) {
                uint32_t b0 = __float_as_uint(vp[(ks2 * 8 + k4) * KVS + nt * 8 + g]);
                uint32_t b1 = __float_as_uint(vp[(ks2 * 8 + k4 + 4) * KVS + nt * 8 + g]);
                mma_tf32(o[0][nt], af[0], b0, b1);
                mma_tf32(o[1][nt], af[1], b0, b1);
            }
        }
        // no trailing barrier: next top-of-loop sync orders O(t) before S(t+1)
        // and before any reuse of this buffer by prefetch(t+2)
    }

    // ---- epilogue: write ctx ----
#pragma unroll
    for (int mt = 0; mt < 2; mt++) {
        size_t row0 = (size_t)(b * T_SEQ + q0 + mt * 16 + g) * D_MOD;
        size_t row1 = row0 + 8 * D_MOD;
#pragma unroll
        for (int nt = 0; nt < 8; nt++) {
            int col = h * HD + nt * 8 + 2 * k4;
            *(float2*)(CTX + row0 + col) = make_float2(o[mt][nt][0], o[mt][nt][1]);
            *(float2*)(CTX + row1 + col) = make_float2(o[mt][nt][2], o[mt][nt][3]);
        }
    }
}

// ---------------- launch --------------------------------------------------
extern "C" void kernel_launch(void* const* d_in, const int* in_sizes, int n_in,
                              void* d_out, int out_size)
{
    const float* q  = (const float*)d_in[0];
    const float* k  = (const float*)d_in[1];
    const float* v  = (const float*)d_in[2];
    const float* Wq = (const float*)d_in[3];
    const float* bq = (const float*)d_in[4];
    const float* Wk = (const float*)d_in[5];
    const float* bk = (const float*)d_in[6];
    // d_in[7]=Wv, d_in[8]=bv : intentionally unused (reference bug preserved)
    const float* Wc = (const float*)d_in[9];
    const float* bc = (const float*)d_in[10];
    float* out = (float*)d_out;

    float *QPd, *KPd, *VPd, *CTXd, *Whid, *Wlod;
    cudaGetSymbolAddress((void**)&QPd,  g_QP);
    cudaGetSymbolAddress((void**)&KPd,  g_KP);
    cudaGetSymbolAddress((void**)&VPd,  g_VP);
    cudaGetSymbolAddress((void**)&CTXd, g_CTX);
    cudaGetSymbolAddress((void**)&Whid, g_Whi);
    cudaGetSymbolAddress((void**)&Wlod, g_Wlo);

    cudaFuncSetAttribute(attn_mma_kernel,
                         cudaFuncAttributeMaxDynamicSharedMemorySize,
                         ATTN_SMEM_BYTES);
    cudaFuncSetAttribute(proj_kernel,
                         cudaFuncAttributeMaxDynamicSharedMemorySize,
                         GSM_BYTES);
    cudaFuncSetAttribute(out_gemm_kernel,
                         cudaFuncAttributeMaxDynamicSharedMemorySize,
                         GSM_BYTES);

    // 0) split weights into hi/lo tf32 pairs (Wq, Wk, Wc)
    split_w_kernel<<<3 * W_ELEMS / 256, 256>>>(Wq, Wk, Wc, Whid, Wlod);

    // 1) fused projections (2xTF32 split): z picks {qp, kp, vp}
    dim3 pgrid(M_ROWS / GBM, D_MOD / GBN, 3);   // (64, 4, 3)
    proj_kernel<<<pgrid, 256, GSM_BYTES>>>(q, k, v, Whid, Wlod, bq, bk,
                                           QPd, KPd, VPd);

    // 2) fused attention (head-axis softmax)
    attn_mma_kernel<<<dim3(T_SEQ / TQa, B_SZ), 256, ATTN_SMEM_BYTES>>>(
        QPd, KPd, VPd, CTXd);

    // 3) output projection (2xTF32 split)
    dim3 ggrid(M_ROWS / GBM, D_MOD / GBN);      // (64, 4)
    out_gemm_kernel<<<ggrid, 256, GSM_BYTES>>>(CTXd, Whid, Wlod, bc, out);
}